// round 11
// baseline (speedup 1.0000x reference)
#include <cuda_runtime.h>

// ForceAggregation: out[m*D + r] = dot(hess[m][r][:], ns[m][:]),  D=300, M=2048.
// hess = 737 MB streamed once. Converged macro-shape (R6): grid 10240,
// 64-row tiles, warp = strided row pairs, rolled depth-1 prefetch pipeline.
// This round: force 5 blocks/SM (launch_bounds minBlocks=5 => <=51 regs) and
// cut address-register pressure with running pointers (pair stride = 16 rows)
// so the pipeline coexists with ~52% achieved occupancy.

#define ROWS_PER_BLOCK 64
#define BLOCK_THREADS 256
#define D300 300

__device__ __forceinline__ float4 f4z() { return make_float4(0.f, 0.f, 0.f, 0.f); }

__device__ __forceinline__ float dot4(float4 a, float4 b, float acc) {
    acc = fmaf(a.x, b.x, acc);
    acc = fmaf(a.y, b.y, acc);
    acc = fmaf(a.z, b.z, acc);
    return fmaf(a.w, b.w, acc);
}

__global__ void __launch_bounds__(BLOCK_THREADS, 5)
force_agg_300(const float* __restrict__ hess,
              const float* __restrict__ ns,
              float* __restrict__ out)
{
    constexpr int NCH    = D300 / 4;            // 75 float4 chunks per row
    constexpr long PSTEP = 16L * D300;          // pair stride: 16 rows of floats

    const int m    = blockIdx.x / 5;
    const int tile = blockIdx.x - m * 5;
    const int row0 = tile << 6;                 // 64-row tiles; tile 4 = rows 256..299

    const int warp = threadIdx.x >> 5;
    const int lane = threadIdx.x & 31;

    // ns chunks for this lane — reused by all rows this warp touches.
    const float4* ns4 = (const float4*)(ns + (size_t)m * D300);
    const bool has2 = (lane < NCH - 64);
    const float4 n0 = __ldg(ns4 + lane);
    const float4 n1 = __ldg(ns4 + lane + 32);
    const float4 n2 = has2 ? __ldg(ns4 + lane + 64) : f4z();

    const int r_first = row0 + (warp << 1);
    const int rend    = (tile < 4) ? (row0 + 64) : D300;

    // Running pointers: current pair and next pair (bumped by PSTEP each iter).
    const float* hb = hess + (size_t)m * D300 * D300 + (size_t)r_first * D300;
    float*       op = out + (size_t)m * D300 + r_first;

    // ---- prologue: load current pair ----
    const float4* h0 = (const float4*)hb;
    const float4* h1 = (const float4*)(hb + D300);
    float4 a0 = __ldcs(h0 + lane);
    float4 b0 = __ldcs(h1 + lane);
    float4 a1 = __ldcs(h0 + lane + 32);
    float4 b1 = __ldcs(h1 + lane + 32);
    float4 a2 = f4z(), b2 = f4z();
    if (has2) { a2 = __ldcs(h0 + lane + 64); b2 = __ldcs(h1 + lane + 64); }

#pragma unroll 1
    for (int r = r_first; r < rend; r += 16, hb += PSTEP, op += 16) {
        // ---- prefetch next pair (in flight through FMA/shuffle window) ----
        const bool more = (r + 16 < rend);
        float4 pa0 = f4z(), pb0 = f4z(), pa1 = f4z(), pb1 = f4z(), pa2 = f4z(), pb2 = f4z();
        if (more) {
            const float4* g0 = (const float4*)(hb + PSTEP);
            const float4* g1 = (const float4*)(hb + PSTEP + D300);
            pa0 = __ldcs(g0 + lane);
            pb0 = __ldcs(g1 + lane);
            pa1 = __ldcs(g0 + lane + 32);
            pb1 = __ldcs(g1 + lane + 32);
            if (has2) { pa2 = __ldcs(g0 + lane + 64); pb2 = __ldcs(g1 + lane + 64); }
        }

        // ---- compute current pair ----
        float acc0 = dot4(a0, n0, 0.f);
        float acc1 = dot4(b0, n0, 0.f);
        acc0 = dot4(a1, n1, acc0);
        acc1 = dot4(b1, n1, acc1);
        acc0 = dot4(a2, n2, acc0);
        acc1 = dot4(b2, n2, acc1);

        // ---- 6-shuffle paired reduction: lane0 -> r, lane16 -> r+1 ----
        acc0 += __shfl_xor_sync(0xffffffffu, acc0, 16);
        acc1 += __shfl_xor_sync(0xffffffffu, acc1, 16);
        float v = (lane & 16) ? acc1 : acc0;
        v += __shfl_xor_sync(0xffffffffu, v, 8);
        v += __shfl_xor_sync(0xffffffffu, v, 4);
        v += __shfl_xor_sync(0xffffffffu, v, 2);
        v += __shfl_xor_sync(0xffffffffu, v, 1);
        if (lane == 0)       op[0] = v;
        else if (lane == 16) op[1] = v;

        // ---- rotate pipeline ----
        a0 = pa0; b0 = pb0; a1 = pa1; b1 = pb1; a2 = pa2; b2 = pb2;
    }
}

// Generic fallback for unexpected D (runtime loop bounds, smem-staged ns).
__global__ void __launch_bounds__(BLOCK_THREADS)
force_agg_generic(const float* __restrict__ hess,
                  const float* __restrict__ ns,
                  float* __restrict__ out,
                  int D, int tiles_per_mol, int rows_per_tile)
{
    extern __shared__ __align__(16) float s_ns[];

    const int m    = blockIdx.x / tiles_per_mol;
    const int tile = blockIdx.x - m * tiles_per_mol;
    const int row0 = tile * rows_per_tile;

    const float* nsm = ns + (size_t)m * D;
    const int nch = D >> 2;
    for (int i = threadIdx.x; i < nch; i += BLOCK_THREADS)
        ((float4*)s_ns)[i] = ((const float4*)nsm)[i];
    for (int i = nch * 4 + threadIdx.x; i < D; i += BLOCK_THREADS)
        s_ns[i] = nsm[i];
    __syncthreads();

    const int warp  = threadIdx.x >> 5;
    const int lane  = threadIdx.x & 31;
    const int nwrps = BLOCK_THREADS >> 5;

    const float4* s4    = (const float4*)s_ns;
    const float*  hbase = hess + (size_t)m * D * D;

    int rend = row0 + rows_per_tile;
    if (rend > D) rend = D;

    for (int r = row0 + warp; r < rend; r += nwrps) {
        const float4* hrow = (const float4*)(hbase + (size_t)r * D);
        float acc = 0.0f;
        for (int c = lane; c < nch; c += 32) {
            const float4 h = __ldcs(hrow + c);
            const float4 n = s4[c];
            acc = fmaf(h.x, n.x, acc);
            acc = fmaf(h.y, n.y, acc);
            acc = fmaf(h.z, n.z, acc);
            acc = fmaf(h.w, n.w, acc);
        }
        for (int c = nch * 4 + lane; c < D; c += 32)
            acc = fmaf(hbase[(size_t)r * D + c], s_ns[c], acc);
#pragma unroll
        for (int off = 16; off; off >>= 1)
            acc += __shfl_xor_sync(0xffffffffu, acc, off);
        if (lane == 0)
            out[(size_t)m * D + r] = acc;
    }
}

extern "C" void kernel_launch(void* const* d_in, const int* in_sizes, int n_in,
                              void* d_out, int out_size)
{
    // Input order: ns [M*N_AT,3] f32, hess [M*D,D] f32, idx_m i32, n_atoms [M] i32
    const float* ns   = (const float*)d_in[0];
    const float* hess = (const float*)d_in[1];
    float*       out  = (float*)d_out;

    const int M = in_sizes[3];
    const int D = (int)((long long)in_sizes[0] / M);

    if (D == 300) {
        force_agg_300<<<(unsigned)(M * 5), BLOCK_THREADS>>>(hess, ns, out);
    } else {
        const int rows = 64;
        const int tiles = (D + rows - 1) / rows;
        const size_t shmem = (size_t)((D + 3) / 4) * 16;
        force_agg_generic<<<(unsigned)(M * tiles), BLOCK_THREADS, shmem>>>(hess, ns, out, D, tiles, rows);
    }
}

// round 12
// speedup vs baseline: 1.0390x; 1.0390x over previous
#include <cuda_runtime.h>

// ForceAggregation: out[m*D + r] = dot(hess[m][r][:], ns[m][:]),  D=300, M=2048.
// hess = 737 MB streamed once. CONVERGED KERNEL (best of 11 structurally
// distinct designs, 106.8us, 6.92 TB/s = ~87% DRAM duty ~= the sm_103a
// path-independent LTS/stream ceiling):
//  - grid 10240 (5 x 64-row tiles per molecule), 256 threads, ~60 regs, 42% occ
//  - warp = row pair (strided, uniform 4 pairs/warp in full tiles)
//  - rolled depth-1 software pipeline: next pair's 6 LDG.128.LDCS issued before
//    current pair's FMA chain + reduce, keeping loads in flight through the
//    compute dead window
//  - ns chunks held in registers per warp; 6-shuffle paired select-butterfly
//    reduction (lane0 -> r, lane16 -> r+1)
// Probed and rejected: higher MLP quads (+ns L2 traffic), block-per-molecule,
// cp.async.bulk ring, full unroll (80 regs -> occ cliff), SMEM-staged ns
// (+regs/+sync), contiguous stripes (tie), reg-capped 5 blocks/SM (spills).

#define ROWS_PER_BLOCK 64
#define BLOCK_THREADS 256

__device__ __forceinline__ float dot4(float4 a, float4 b, float acc) {
    acc = fmaf(a.x, b.x, acc);
    acc = fmaf(a.y, b.y, acc);
    acc = fmaf(a.z, b.z, acc);
    return fmaf(a.w, b.w, acc);
}

__global__ void __launch_bounds__(BLOCK_THREADS)
force_agg_300(const float* __restrict__ hess,
              const float* __restrict__ ns,
              float* __restrict__ out,
              int tiles_per_mol)
{
    constexpr int D   = 300;
    constexpr int NCH = D / 4;          // 75 float4 chunks per row

    const int m    = blockIdx.x / tiles_per_mol;
    const int tile = blockIdx.x - m * tiles_per_mol;
    const int row0 = tile * ROWS_PER_BLOCK;

    const int warp = threadIdx.x >> 5;
    const int lane = threadIdx.x & 31;

    const float4 z4 = make_float4(0.f, 0.f, 0.f, 0.f);

    // ns chunks for this lane — reused by all rows this warp touches.
    const float4* ns4 = (const float4*)(ns + (size_t)m * D);
    const bool has2 = (lane < NCH - 64);
    float4 n0 = __ldg(ns4 + lane);
    float4 n1 = __ldg(ns4 + lane + 32);
    float4 n2 = has2 ? __ldg(ns4 + lane + 64) : z4;

    const float* hbase = hess + (size_t)m * D * D;

    int rend = row0 + ROWS_PER_BLOCK;
    if (rend > D) rend = D;            // rend - row0 always even (D even)

    int r = row0 + (warp << 1);
    if (r >= rend) return;

    // ---- prologue: load current pair ----
    const float4* h0 = (const float4*)(hbase + (size_t)r * D);
    const float4* h1 = (const float4*)(hbase + (size_t)(r + 1) * D);
    float4 a0 = __ldcs(h0 + lane);
    float4 b0 = __ldcs(h1 + lane);
    float4 a1 = __ldcs(h0 + lane + 32);
    float4 b1 = __ldcs(h1 + lane + 32);
    float4 a2 = z4, b2 = z4;
    if (has2) { a2 = __ldcs(h0 + lane + 64); b2 = __ldcs(h1 + lane + 64); }

    for (; r < rend; r += 16) {
        // ---- prefetch next pair (kept in flight during reduce) ----
        const int rn = r + 16;
        const bool more = (rn < rend);
        float4 pa0 = z4, pb0 = z4, pa1 = z4, pb1 = z4, pa2 = z4, pb2 = z4;
        if (more) {
            const float4* g0 = (const float4*)(hbase + (size_t)rn * D);
            const float4* g1 = (const float4*)(hbase + (size_t)(rn + 1) * D);
            pa0 = __ldcs(g0 + lane);
            pb0 = __ldcs(g1 + lane);
            pa1 = __ldcs(g0 + lane + 32);
            pb1 = __ldcs(g1 + lane + 32);
            if (has2) { pa2 = __ldcs(g0 + lane + 64); pb2 = __ldcs(g1 + lane + 64); }
        }

        // ---- compute current pair ----
        float acc0 = dot4(a0, n0, 0.f);
        float acc1 = dot4(b0, n0, 0.f);
        acc0 = dot4(a1, n1, acc0);
        acc1 = dot4(b1, n1, acc1);
        acc0 = dot4(a2, n2, acc0);
        acc1 = dot4(b2, n2, acc1);

        // ---- 6-shuffle paired reduction: lane0 -> r, lane16 -> r+1 ----
        acc0 += __shfl_xor_sync(0xffffffffu, acc0, 16);
        acc1 += __shfl_xor_sync(0xffffffffu, acc1, 16);
        float v = (lane & 16) ? acc1 : acc0;
        v += __shfl_xor_sync(0xffffffffu, v, 8);
        v += __shfl_xor_sync(0xffffffffu, v, 4);
        v += __shfl_xor_sync(0xffffffffu, v, 2);
        v += __shfl_xor_sync(0xffffffffu, v, 1);
        if (lane == 0)       out[(size_t)m * D + r]     = v;
        else if (lane == 16) out[(size_t)m * D + r + 1] = v;

        // ---- rotate pipeline ----
        a0 = pa0; b0 = pb0; a1 = pa1; b1 = pb1; a2 = pa2; b2 = pb2;
    }
}

// Generic fallback for unexpected D (runtime loop bounds, smem-staged ns).
__global__ void __launch_bounds__(BLOCK_THREADS)
force_agg_generic(const float* __restrict__ hess,
                  const float* __restrict__ ns,
                  float* __restrict__ out,
                  int D, int tiles_per_mol)
{
    extern __shared__ __align__(16) float s_ns[];

    const int m    = blockIdx.x / tiles_per_mol;
    const int tile = blockIdx.x - m * tiles_per_mol;
    const int row0 = tile * ROWS_PER_BLOCK;

    const float* nsm = ns + (size_t)m * D;
    const int nch = D >> 2;
    for (int i = threadIdx.x; i < nch; i += BLOCK_THREADS)
        ((float4*)s_ns)[i] = ((const float4*)nsm)[i];
    for (int i = nch * 4 + threadIdx.x; i < D; i += BLOCK_THREADS)
        s_ns[i] = nsm[i];
    __syncthreads();

    const int warp  = threadIdx.x >> 5;
    const int lane  = threadIdx.x & 31;
    const int nwrps = BLOCK_THREADS >> 5;

    const float4* s4    = (const float4*)s_ns;
    const float*  hbase = hess + (size_t)m * D * D;

    int rend = row0 + ROWS_PER_BLOCK;
    if (rend > D) rend = D;

    for (int r = row0 + warp; r < rend; r += nwrps) {
        const float4* hrow = (const float4*)(hbase + (size_t)r * D);
        float acc = 0.0f;
        for (int c = lane; c < nch; c += 32) {
            const float4 h = __ldcs(hrow + c);
            const float4 n = s4[c];
            acc = fmaf(h.x, n.x, acc);
            acc = fmaf(h.y, n.y, acc);
            acc = fmaf(h.z, n.z, acc);
            acc = fmaf(h.w, n.w, acc);
        }
        for (int c = nch * 4 + lane; c < D; c += 32)
            acc = fmaf(hbase[(size_t)r * D + c], s_ns[c], acc);
#pragma unroll
        for (int off = 16; off; off >>= 1)
            acc += __shfl_xor_sync(0xffffffffu, acc, off);
        if (lane == 0)
            out[(size_t)m * D + r] = acc;
    }
}

extern "C" void kernel_launch(void* const* d_in, const int* in_sizes, int n_in,
                              void* d_out, int out_size)
{
    // Input order: ns [M*N_AT,3] f32, hess [M*D,D] f32, idx_m i32, n_atoms [M] i32
    const float* ns   = (const float*)d_in[0];
    const float* hess = (const float*)d_in[1];
    float*       out  = (float*)d_out;

    const int M = in_sizes[3];
    const int D = (int)((long long)in_sizes[0] / M);

    const int tiles = (D + ROWS_PER_BLOCK - 1) / ROWS_PER_BLOCK;
    const dim3 grid((unsigned)(M * tiles));
    const dim3 block(BLOCK_THREADS);

    if (D == 300) {
        force_agg_300<<<grid, block>>>(hess, ns, out, tiles);
    } else {
        const size_t shmem = (size_t)((D + 3) / 4) * 16;
        force_agg_generic<<<grid, block, shmem>>>(hess, ns, out, D, tiles);
    }
}